// round 17
// baseline (speedup 1.0000x reference)
#include <cuda_runtime.h>
#include <cstdint>

// Embedding gather via cp.async.cg fills + smem drain (sm_103a).
// x: [32768] int32; emb: [50257, 512] f32; out: [32768, 512] f32.
// even ids -> id 0 (reference: jnp.where(x % 2 == 0, 0, x)).
//
// Read side: 8x cp.async.cg 16B per thread (LDGSTS, L1-bypass) into a
//   32KB smem tile. No register writeback, no scoreboard stall per load --
//   the warp issues all 8 and waits ONCE. This finally exposes full MLP
//   without the 32-reg ceiling that capped every LDG-based variant.
// Write side: LDS.128 -> STG.128 drain (smem hit = 29cyc, cheap).
// 6 CTAs/SM (32KB tiles) keep fill and drain phases overlapped chip-wide.

static constexpr int ROW_BYTES      = 2048;   // 512 f32
static constexpr int ROWS_PER_BLOCK = 16;
static constexpr int THREADS        = 256;
static constexpr int TILE_VECS      = ROWS_PER_BLOCK * 128;   // 2048 float4
static constexpr int CHUNKS         = 8;      // per-thread fills/drains

__device__ __forceinline__ uint32_t smem_u32(const void* p) {
    return (uint32_t)__cvta_generic_to_shared(p);
}

__global__ __launch_bounds__(THREADS)
void embed_gather_kernel(const int* __restrict__ x,
                         const float4* __restrict__ emb,
                         float4* __restrict__ out) {
    __shared__ alignas(128) float4 stage[TILE_VECS];   // 32 KB

    const int base = blockIdx.x * ROWS_PER_BLOCK;
    const int tid  = threadIdx.x;

    // chunk c covers rows {2c, 2c+1}: threads 0..127 -> row 2c,
    // threads 128..255 -> row 2c+1; col = tid & 127 (128B/warp coalesced).
    const int rhi = tid >> 7;         // warp-uniform
    const int col = tid & 127;

    const uint32_t s0 = smem_u32(stage) + (uint32_t)tid * 16;

#pragma unroll
    for (int c = 0; c < CHUNKS; c++) {
        int tok = __ldg(x + base + 2 * c + rhi);   // warp-uniform broadcast
        tok = (tok & 1) ? tok : 0;                 // even ids -> row 0
        const char* src = (const char*)(emb + (size_t)tok * 128 + col);
        asm volatile("cp.async.cg.shared.global [%0], [%1], 16;"
                     :: "r"(s0 + c * THREADS * 16), "l"(src) : "memory");
    }
    asm volatile("cp.async.commit_group;" ::: "memory");
    asm volatile("cp.async.wait_group 0;" ::: "memory");
    __syncthreads();

    // Drain: smem tile layout == gmem layout of the 16 consecutive rows.
    float4* dst = out + (size_t)base * 128 + tid;
#pragma unroll
    for (int c = 0; c < CHUNKS; c++)
        dst[c * THREADS] = stage[c * THREADS + tid];
}

extern "C" void kernel_launch(void* const* d_in, const int* in_sizes, int n_in,
                              void* d_out, int out_size) {
    const int* x      = (const int*)d_in[0];
    const float4* emb = (const float4*)d_in[1];
    float4* out       = (float4*)d_out;

    int n_rows   = in_sizes[0];                    // 32768
    int n_blocks = n_rows / ROWS_PER_BLOCK;        // 2048

    embed_gather_kernel<<<n_blocks, THREADS>>>(x, emb, out);
}